// round 5
// baseline (speedup 1.0000x reference)
#include <cuda_runtime.h>
#include <cuda_bf16.h>
#include <cstdint>

#define B_ 4
#define S_ 2048
#define DIN_ 1024
#define H_ 16
#define E_ 64

// Scratch for Q/K/V: [B,H,S,E] each = 33.5 MB (static __device__, allowed)
__device__ float g_Q[B_*H_*S_*E_];
__device__ float g_K[B_*H_*S_*E_];
__device__ float g_V[B_*H_*S_*E_];

// ---------------------------------------------------------------------------
// MMA helpers (bf16 m16n8k16, fp32 accumulate)
// ---------------------------------------------------------------------------
__device__ __forceinline__ void mma_bf16_16816(float c[4],
    const uint32_t a[4], uint32_t b0, uint32_t b1)
{
    asm volatile(
        "mma.sync.aligned.m16n8k16.row.col.f32.bf16.bf16.f32 "
        "{%0,%1,%2,%3}, {%4,%5,%6,%7}, {%8,%9}, {%0,%1,%2,%3};"
        : "+f"(c[0]), "+f"(c[1]), "+f"(c[2]), "+f"(c[3])
        : "r"(a[0]), "r"(a[1]), "r"(a[2]), "r"(a[3]), "r"(b0), "r"(b1));
}

__device__ __forceinline__ void ldsm_x4(uint32_t& r0, uint32_t& r1,
                                        uint32_t& r2, uint32_t& r3, uint32_t addr)
{
    asm volatile("ldmatrix.sync.aligned.m8n8.x4.shared.b16 {%0,%1,%2,%3}, [%4];"
                 : "=r"(r0), "=r"(r1), "=r"(r2), "=r"(r3) : "r"(addr));
}

__device__ __forceinline__ void ldsm_x4_t(uint32_t& r0, uint32_t& r1,
                                          uint32_t& r2, uint32_t& r3, uint32_t addr)
{
    asm volatile("ldmatrix.sync.aligned.m8n8.x4.trans.shared.b16 {%0,%1,%2,%3}, [%4];"
                 : "=r"(r0), "=r"(r1), "=r"(r2), "=r"(r3) : "r"(addr));
}

__device__ __forceinline__ uint32_t pack_bf2(__nv_bfloat16 a, __nv_bfloat16 b)
{
    __nv_bfloat162 t = __halves2bfloat162(a, b);   // a = low half, b = high half
    return *reinterpret_cast<uint32_t*>(&t);
}

__device__ __forceinline__ void split_f32(float x, __nv_bfloat16& hi, __nv_bfloat16& lo)
{
    hi = __float2bfloat16(x);
    lo = __float2bfloat16(x - __bfloat162float(hi));
}

// ---------------------------------------------------------------------------
// Kernel 1: QKV projection via bf16 split-precision tensor-core MMA.
// Block tile 128(M) x 64(N), K-tile 32. 256 threads = 8 warps in 4(M) x 2(N).
// C += Ahi*Bhi + Ahi*Blo + Alo*Bhi  (drop lo*lo, <=2^-18 rel).
// ---------------------------------------------------------------------------
#define BM 128
#define BK 32
#define XS_STR 40   // bf16 elems/row (32+8 pad) -> 80B rows, LDSM conflict-free
#define WS_STR 72   // bf16 elems/row (64+8 pad) -> 144B rows, conflict-free

__global__ __launch_bounds__(256) void proj_mma_kernel(
    const float* __restrict__ X,
    const float* __restrict__ Wq,
    const float* __restrict__ Wk,
    const float* __restrict__ Wv)
{
    __shared__ __nv_bfloat16 XsHi[BM * XS_STR];
    __shared__ __nv_bfloat16 XsLo[BM * XS_STR];
    __shared__ __nv_bfloat16 WsHi[BK * WS_STR];
    __shared__ __nv_bfloat16 WsLo[BK * WS_STR];

    const int tid  = threadIdx.x;
    const int wid  = tid >> 5;
    const int lane = tid & 31;
    const int wm = wid >> 1;        // 0..3 -> rows wm*32
    const int wn = wid & 1;         // 0..1 -> cols wn*32

    const int b     = blockIdx.z / 3;
    const int which = blockIdx.z % 3;
    const int h     = blockIdx.y;
    const int m0    = blockIdx.x * BM;

    const float* Xb = X + (size_t)b * S_ * DIN_;
    const float* W  = (which == 0 ? Wq : which == 1 ? Wk : Wv) + (size_t)h * DIN_ * E_;
    float* Out = (which == 0 ? g_Q : which == 1 ? g_K : g_V)
               + ((size_t)(b * H_ + h) * S_) * E_;

    float c[2][4][4];
    #pragma unroll
    for (int mi = 0; mi < 2; mi++)
        #pragma unroll
        for (int ni = 0; ni < 4; ni++)
            #pragma unroll
            for (int r = 0; r < 4; r++) c[mi][ni][r] = 0.f;

    const int lrow  = lane & 15;
    const int lcol8 = (lane >> 4) * 8;

    const uint32_t xhiB = (uint32_t)__cvta_generic_to_shared(XsHi);
    const uint32_t xloB = (uint32_t)__cvta_generic_to_shared(XsLo);
    const uint32_t whiB = (uint32_t)__cvta_generic_to_shared(WsHi);
    const uint32_t wloB = (uint32_t)__cvta_generic_to_shared(WsLo);

    uint32_t offA[2];
    #pragma unroll
    for (int mi = 0; mi < 2; mi++)
        offA[mi] = (uint32_t)(((wm * 32 + mi * 16 + lrow) * XS_STR + lcol8) * 2);
    uint32_t offB[2];
    #pragma unroll
    for (int nt = 0; nt < 2; nt++)
        offB[nt] = (uint32_t)((lrow * WS_STR + wn * 32 + nt * 16 + lcol8) * 2);

    for (int k0 = 0; k0 < DIN_; k0 += BK) {
        #pragma unroll
        for (int j = 0; j < 4; j++) {
            int id  = tid + 256 * j;      // 0..1023
            int row = id >> 3;            // 0..127
            int col = (id & 7) * 4;       // 0..28
            float4 v = *(const float4*)&Xb[(size_t)(m0 + row) * DIN_ + k0 + col];
            __nv_bfloat16 h0, h1, h2, h3, l0, l1, l2, l3;
            split_f32(v.x, h0, l0); split_f32(v.y, h1, l1);
            split_f32(v.z, h2, l2); split_f32(v.w, h3, l3);
            *(uint2*)&XsHi[row * XS_STR + col] = make_uint2(pack_bf2(h0,h1), pack_bf2(h2,h3));
            *(uint2*)&XsLo[row * XS_STR + col] = make_uint2(pack_bf2(l0,l1), pack_bf2(l2,l3));
        }
        #pragma unroll
        for (int j = 0; j < 2; j++) {
            int id  = tid + 256 * j;      // 0..511
            int row = id >> 4;            // 0..31
            int col = (id & 15) * 4;      // 0..60
            float4 v = *(const float4*)&W[(size_t)(k0 + row) * E_ + col];
            __nv_bfloat16 h0, h1, h2, h3, l0, l1, l2, l3;
            split_f32(v.x, h0, l0); split_f32(v.y, h1, l1);
            split_f32(v.z, h2, l2); split_f32(v.w, h3, l3);
            *(uint2*)&WsHi[row * WS_STR + col] = make_uint2(pack_bf2(h0,h1), pack_bf2(h2,h3));
            *(uint2*)&WsLo[row * WS_STR + col] = make_uint2(pack_bf2(l0,l1), pack_bf2(l2,l3));
        }
        __syncthreads();

        #pragma unroll
        for (int ks = 0; ks < 2; ks++) {
            const uint32_t aKoff = (uint32_t)(ks * 16 * 2);
            const uint32_t bKoff = (uint32_t)(ks * 16 * WS_STR * 2);

            uint32_t ah[2][4], al[2][4];
            #pragma unroll
            for (int mi = 0; mi < 2; mi++) {
                ldsm_x4(ah[mi][0], ah[mi][1], ah[mi][2], ah[mi][3], xhiB + offA[mi] + aKoff);
                ldsm_x4(al[mi][0], al[mi][1], al[mi][2], al[mi][3], xloB + offA[mi] + aKoff);
            }
            uint32_t bh[4][2], bl[4][2];
            #pragma unroll
            for (int nt = 0; nt < 2; nt++) {
                uint32_t r0, r1, r2, r3;
                ldsm_x4_t(r0, r1, r2, r3, whiB + offB[nt] + bKoff);
                bh[2*nt][0] = r0; bh[2*nt][1] = r1; bh[2*nt+1][0] = r2; bh[2*nt+1][1] = r3;
                ldsm_x4_t(r0, r1, r2, r3, wloB + offB[nt] + bKoff);
                bl[2*nt][0] = r0; bl[2*nt][1] = r1; bl[2*nt+1][0] = r2; bl[2*nt+1][1] = r3;
            }
            #pragma unroll
            for (int mi = 0; mi < 2; mi++) {
                #pragma unroll
                for (int ni = 0; ni < 4; ni++) {
                    mma_bf16_16816(c[mi][ni], ah[mi], bh[ni][0], bh[ni][1]);
                    mma_bf16_16816(c[mi][ni], ah[mi], bl[ni][0], bl[ni][1]);
                    mma_bf16_16816(c[mi][ni], al[mi], bh[ni][0], bh[ni][1]);
                }
            }
        }
        __syncthreads();
    }

    const int crow = lane >> 2;
    const int ccol = (lane & 3) * 2;
    #pragma unroll
    for (int mi = 0; mi < 2; mi++) {
        #pragma unroll
        for (int ni = 0; ni < 4; ni++) {
            int row = m0 + wm * 32 + mi * 16 + crow;
            int col = wn * 32 + ni * 8 + ccol;
            *(float2*)&Out[(size_t)row * E_ + col]       = make_float2(c[mi][ni][0], c[mi][ni][1]);
            *(float2*)&Out[(size_t)(row + 8) * E_ + col] = make_float2(c[mi][ni][2], c[mi][ni][3]);
        }
    }
}

// ---------------------------------------------------------------------------
// Kernel 2: causal flash attention, bf16 split-precision tensor cores.
// Block = (64 q rows, h, b); 128 threads = 4 warps, warp w owns q rows w*16..+15.
// Key tiles of 32. Q/K/V all split hi+lo in smem; S and PV both 3-term MMA.
// S C-fragment layout == P A-fragment layout: P never round-trips smem.
// ---------------------------------------------------------------------------
#define A_STR 72    // 144B rows: conflict-free ldmatrix

__global__ __launch_bounds__(128) void attn_mma_kernel(float* __restrict__ out)
{
    __shared__ __nv_bfloat16 QHi[64 * A_STR], QLo[64 * A_STR];
    __shared__ __nv_bfloat16 KHi[32 * A_STR], KLo[32 * A_STR];
    __shared__ __nv_bfloat16 VHi[32 * A_STR], VLo[32 * A_STR];

    const int tid  = threadIdx.x;
    const int lane = tid & 31;
    const int wid  = tid >> 5;          // 0..3
    const int qt = blockIdx.x;          // 0..31
    const int h  = blockIdx.y;
    const int b  = blockIdx.z;
    const size_t bh = (size_t)(b * H_ + h);
    const float* Qp = g_Q + bh * S_ * E_;
    const float* Kp = g_K + bh * S_ * E_;
    const float* Vp = g_V + bh * S_ * E_;
    const int qbase = qt * 64;

    // stage Q (pre-scaled by 1/sqrt(64)=0.125), split hi/lo
    #pragma unroll
    for (int t = 0; t < 8; t++) {
        int id  = tid + 128 * t;        // 0..1023
        int row = id >> 4;              // 0..63
        int col = (id & 15) * 4;        // 0..60
        float4 v = *(const float4*)&Qp[(size_t)(qbase + row) * E_ + col];
        v.x *= 0.125f; v.y *= 0.125f; v.z *= 0.125f; v.w *= 0.125f;
        __nv_bfloat16 h0, h1, h2, h3, l0, l1, l2, l3;
        split_f32(v.x, h0, l0); split_f32(v.y, h1, l1);
        split_f32(v.z, h2, l2); split_f32(v.w, h3, l3);
        *(uint2*)&QHi[row * A_STR + col] = make_uint2(pack_bf2(h0,h1), pack_bf2(h2,h3));
        *(uint2*)&QLo[row * A_STR + col] = make_uint2(pack_bf2(l0,l1), pack_bf2(l2,l3));
    }
    __syncthreads();

    const uint32_t qhiB = (uint32_t)__cvta_generic_to_shared(QHi);
    const uint32_t qloB = (uint32_t)__cvta_generic_to_shared(QLo);
    const uint32_t khiB = (uint32_t)__cvta_generic_to_shared(KHi);
    const uint32_t kloB = (uint32_t)__cvta_generic_to_shared(KLo);
    const uint32_t vhiB = (uint32_t)__cvta_generic_to_shared(VHi);
    const uint32_t vloB = (uint32_t)__cvta_generic_to_shared(VLo);

    const int lrow  = lane & 15;
    const int lcol8 = (lane >> 4) * 8;

    // Q fragments: A layout, 4 k16 steps over E=64, held for whole kernel
    uint32_t qh[4][4], ql[4][4];
    #pragma unroll
    for (int ks = 0; ks < 4; ks++) {
        uint32_t off = (uint32_t)(((wid * 16 + lrow) * A_STR + ks * 16 + lcol8) * 2);
        ldsm_x4(qh[ks][0], qh[ks][1], qh[ks][2], qh[ks][3], qhiB + off);
        ldsm_x4(ql[ks][0], ql[ks][1], ql[ks][2], ql[ks][3], qloB + off);
    }

    float o[8][4];
    #pragma unroll
    for (int nt = 0; nt < 8; nt++)
        #pragma unroll
        for (int r = 0; r < 4; r++) o[nt][r] = 0.f;
    float mr0 = -1e30f, mr1 = -1e30f, lr0 = 0.f, lr1 = 0.f;

    // K non-trans B-frag address pieces: rows = keys, cols = e
    const int knrow = (lane & 7) + ((lane >> 4) & 1) * 8;  // key row in 16-block
    const int kksel = ((lane >> 3) & 1) * 8;               // e 8-col half

    const int nkt = 2 * qt + 2;
    for (int kt = 0; kt < nkt; kt++) {
        const int kbase = kt * 32;
        __syncthreads();   // prior-iter smem reads done before overwrite

        // load K/V tiles 32x64, split
        #pragma unroll
        for (int t = 0; t < 4; t++) {
            int id  = tid + 128 * t;    // 0..511
            int row = id >> 4;          // 0..31
            int col = (id & 15) * 4;
            float4 kv = *(const float4*)&Kp[(size_t)(kbase + row) * E_ + col];
            __nv_bfloat16 h0, h1, h2, h3, l0, l1, l2, l3;
            split_f32(kv.x, h0, l0); split_f32(kv.y, h1, l1);
            split_f32(kv.z, h2, l2); split_f32(kv.w, h3, l3);
            *(uint2*)&KHi[row * A_STR + col] = make_uint2(pack_bf2(h0,h1), pack_bf2(h2,h3));
            *(uint2*)&KLo[row * A_STR + col] = make_uint2(pack_bf2(l0,l1), pack_bf2(l2,l3));
            float4 vv = *(const float4*)&Vp[(size_t)(kbase + row) * E_ + col];
            split_f32(vv.x, h0, l0); split_f32(vv.y, h1, l1);
            split_f32(vv.z, h2, l2); split_f32(vv.w, h3, l3);
            *(uint2*)&VHi[row * A_STR + col] = make_uint2(pack_bf2(h0,h1), pack_bf2(h2,h3));
            *(uint2*)&VLo[row * A_STR + col] = make_uint2(pack_bf2(l0,l1), pack_bf2(l2,l3));
        }
        __syncthreads();

        // warp skips tiles that are entirely above its causal diagonal
        if (kbase > qbase + wid * 16 + 15) continue;

        // ---- S = Qs @ K^T  (4 n8-tiles over 32 keys) ----
        float s[4][4];
        #pragma unroll
        for (int nt = 0; nt < 4; nt++)
            #pragma unroll
            for (int r = 0; r < 4; r++) s[nt][r] = 0.f;

        #pragma unroll
        for (int ks = 0; ks < 4; ks++) {
            uint32_t kbh[4][2], kbl[4][2];
            #pragma unroll
            for (int np = 0; np < 2; np++) {
                uint32_t off = (uint32_t)(((np * 16 + knrow) * A_STR + ks * 16 + kksel) * 2);
                uint32_t r0, r1, r2, r3;
                ldsm_x4(r0, r1, r2, r3, khiB + off);
                kbh[2*np][0] = r0; kbh[2*np][1] = r1; kbh[2*np+1][0] = r2; kbh[2*np+1][1] = r3;
                ldsm_x4(r0, r1, r2, r3, kloB + off);
                kbl[2*np][0] = r0; kbl[2*np][1] = r1; kbl[2*np+1][0] = r2; kbl[2*np+1][1] = r3;
            }
            #pragma unroll
            for (int nt = 0; nt < 4; nt++) {
                mma_bf16_16816(s[nt], qh[ks], kbh[nt][0], kbh[nt][1]);
                mma_bf16_16816(s[nt], qh[ks], kbl[nt][0], kbl[nt][1]);
                mma_bf16_16816(s[nt], ql[ks], kbh[nt][0], kbh[nt][1]);
            }
        }

        // ---- causal mask ----
        if (kbase + 31 > qbase + wid * 16) {
            int row0 = qbase + wid * 16 + (lane >> 2);
            #pragma unroll
            for (int nt = 0; nt < 4; nt++) {
                int colb = kbase + nt * 8 + (lane & 3) * 2;
                if (colb     > row0)     s[nt][0] = -1e30f;
                if (colb + 1 > row0)     s[nt][1] = -1e30f;
                if (colb     > row0 + 8) s[nt][2] = -1e30f;
                if (colb + 1 > row0 + 8) s[nt][3] = -1e30f;
            }
        }

        // ---- online softmax (rows r=lane/4 in c0/c1, r+8 in c2/c3) ----
        float mx0 = fmaxf(fmaxf(s[0][0], s[0][1]), fmaxf(s[1][0], s[1][1]));
        mx0 = fmaxf(mx0, fmaxf(fmaxf(s[2][0], s[2][1]), fmaxf(s[3][0], s[3][1])));
        float mx1 = fmaxf(fmaxf(s[0][2], s[0][3]), fmaxf(s[1][2], s[1][3]));
        mx1 = fmaxf(mx1, fmaxf(fmaxf(s[2][2], s[2][3]), fmaxf(s[3][2], s[3][3])));
        mx0 = fmaxf(mx0, __shfl_xor_sync(0xffffffffu, mx0, 1));
        mx0 = fmaxf(mx0, __shfl_xor_sync(0xffffffffu, mx0, 2));
        mx1 = fmaxf(mx1, __shfl_xor_sync(0xffffffffu, mx1, 1));
        mx1 = fmaxf(mx1, __shfl_xor_sync(0xffffffffu, mx1, 2));

        float mn0 = fmaxf(mr0, mx0), mn1 = fmaxf(mr1, mx1);
        float a0 = __expf(mr0 - mn0), a1 = __expf(mr1 - mn1);

        float p[4][4];
        float rs0 = 0.f, rs1 = 0.f;
        #pragma unroll
        for (int nt = 0; nt < 4; nt++) {
            p[nt][0] = __expf(s[nt][0] - mn0);
            p[nt][1] = __expf(s[nt][1] - mn0);
            p[nt][2] = __expf(s[nt][2] - mn1);
            p[nt][3] = __expf(s[nt][3] - mn1);
            rs0 += p[nt][0] + p[nt][1];
            rs1 += p[nt][2] + p[nt][3];
        }
        rs0 += __shfl_xor_sync(0xffffffffu, rs0, 1);
        rs0 += __shfl_xor_sync(0xffffffffu, rs0, 2);
        rs1 += __shfl_xor_sync(0xffffffffu, rs1, 1);
        rs1 += __shfl_xor_sync(0xffffffffu, rs1, 2);
        lr0 = lr0 * a0 + rs0;  lr1 = lr1 * a1 + rs1;
        mr0 = mn0;             mr1 = mn1;

        #pragma unroll
        for (int nt = 0; nt < 8; nt++) {
            o[nt][0] *= a0; o[nt][1] *= a0;
            o[nt][2] *= a1; o[nt][3] *= a1;
        }

        // ---- pack P as split A-fragments (2 k16 steps over 32 keys) ----
        uint32_t ph[2][4], pl[2][4];
        #pragma unroll
        for (int ksp = 0; ksp < 2; ksp++) {
            #pragma unroll
            for (int half = 0; half < 2; half++) {
                int nt = 2 * ksp + half;
                __nv_bfloat16 h0, h1, h2, h3, l0, l1, l2, l3;
                split_f32(p[nt][0], h0, l0); split_f32(p[nt][1], h1, l1);
                split_f32(p[nt][2], h2, l2); split_f32(p[nt][3], h3, l3);
                ph[ksp][2*half]     = pack_bf2(h0, h1);   // a0/a2: rows r
                ph[ksp][2*half + 1] = pack_bf2(h2, h3);   // a1/a3: rows r+8
                pl[ksp][2*half]     = pack_bf2(l0, l1);
                pl[ksp][2*half + 1] = pack_bf2(l2, l3);
            }
        }

        // ---- O += P @ V  (8 n8-tiles over E=64) ----
        #pragma unroll
        for (int ksp = 0; ksp < 2; ksp++) {
            #pragma unroll
            for (int ep = 0; ep < 4; ep++) {
                uint32_t off = (uint32_t)(((ksp * 16 + lrow) * A_STR + ep * 16 + lcol8) * 2);
                uint32_t vh0, vh1, vh2, vh3, vl0, vl1, vl2, vl3;
                ldsm_x4_t(vh0, vh1, vh2, vh3, vhiB + off);
                ldsm_x4_t(vl0, vl1, vl2, vl3, vloB + off);
                mma_bf16_16816(o[2*ep],   ph[ksp], vh0, vh1);
                mma_bf16_16816(o[2*ep],   ph[ksp], vl0, vl1);
                mma_bf16_16816(o[2*ep],   pl[ksp], vh0, vh1);
                mma_bf16_16816(o[2*ep+1], ph[ksp], vh2, vh3);
                mma_bf16_16816(o[2*ep+1], ph[ksp], vl2, vl3);
                mma_bf16_16816(o[2*ep+1], pl[ksp], vh2, vh3);
            }
        }
    }

    // ---- epilogue: normalize, write out[b][s][h*64 + e] ----
    float inv0 = 1.f / lr0, inv1 = 1.f / lr1;
    int row0 = qbase + wid * 16 + (lane >> 2);
    int colb = (lane & 3) * 2;
    #pragma unroll
    for (int nt = 0; nt < 8; nt++) {
        int col = h * E_ + nt * 8 + colb;
        *(float2*)&out[((size_t)b * S_ + row0) * (H_ * E_) + col] =
            make_float2(o[nt][0] * inv0, o[nt][1] * inv0);
        *(float2*)&out[((size_t)b * S_ + row0 + 8) * (H_ * E_) + col] =
            make_float2(o[nt][2] * inv1, o[nt][3] * inv1);
    }
}

extern "C" void kernel_launch(void* const* d_in, const int* in_sizes, int n_in,
                              void* d_out, int out_size)
{
    const float* x  = (const float*)d_in[0];
    const float* wq = (const float*)d_in[1];
    const float* wk = (const float*)d_in[2];
    const float* wv = (const float*)d_in[3];
    float* out = (float*)d_out;

    dim3 g1(S_ / BM, H_, B_ * 3);
    proj_mma_kernel<<<g1, 256>>>(x, wq, wk, wv);

    dim3 g2(S_ / 64, H_, B_);
    attn_mma_kernel<<<g2, 128>>>(out);
}

// round 11
// speedup vs baseline: 1.0553x; 1.0553x over previous
#include <cuda_runtime.h>
#include <cuda_bf16.h>
#include <cstdint>

#define B_ 4
#define S_ 2048
#define DIN_ 1024
#define H_ 16
#define E_ 64
#define NROW (B_*S_)     // 8192 rows (b,s)
#define NOUT (H_*E_)     // 1024 cols (h,e)

// Pre-split operands (bf16 hi/lo), produced once per launch
__device__ __nv_bfloat16 g_XHi[NROW*DIN_], g_XLo[NROW*DIN_];
__device__ __nv_bfloat16 g_WHi[3*DIN_*NOUT], g_WLo[3*DIN_*NOUT];
// Q/K/V stored pre-split as [NROW][NOUT] (row = b*S+s, col = h*64+e)
__device__ __nv_bfloat16 g_QHi[NROW*NOUT], g_QLo[NROW*NOUT];
__device__ __nv_bfloat16 g_KHi[NROW*NOUT], g_KLo[NROW*NOUT];
__device__ __nv_bfloat16 g_VHi[NROW*NOUT], g_VLo[NROW*NOUT];

// ---------------------------------------------------------------------------
// helpers
// ---------------------------------------------------------------------------
__device__ __forceinline__ void mma_bf16_16816(float c[4],
    const uint32_t a[4], uint32_t b0, uint32_t b1)
{
    asm volatile(
        "mma.sync.aligned.m16n8k16.row.col.f32.bf16.bf16.f32 "
        "{%0,%1,%2,%3}, {%4,%5,%6,%7}, {%8,%9}, {%0,%1,%2,%3};"
        : "+f"(c[0]), "+f"(c[1]), "+f"(c[2]), "+f"(c[3])
        : "r"(a[0]), "r"(a[1]), "r"(a[2]), "r"(a[3]), "r"(b0), "r"(b1));
}

__device__ __forceinline__ void ldsm_x4(uint32_t& r0, uint32_t& r1,
                                        uint32_t& r2, uint32_t& r3, uint32_t addr)
{
    asm volatile("ldmatrix.sync.aligned.m8n8.x4.shared.b16 {%0,%1,%2,%3}, [%4];"
                 : "=r"(r0), "=r"(r1), "=r"(r2), "=r"(r3) : "r"(addr));
}

__device__ __forceinline__ void ldsm_x4_t(uint32_t& r0, uint32_t& r1,
                                          uint32_t& r2, uint32_t& r3, uint32_t addr)
{
    asm volatile("ldmatrix.sync.aligned.m8n8.x4.trans.shared.b16 {%0,%1,%2,%3}, [%4];"
                 : "=r"(r0), "=r"(r1), "=r"(r2), "=r"(r3) : "r"(addr));
}

__device__ __forceinline__ uint32_t pack_bf2(__nv_bfloat16 a, __nv_bfloat16 b)
{
    __nv_bfloat162 t = __halves2bfloat162(a, b);   // a = low half, b = high half
    return *reinterpret_cast<uint32_t*>(&t);
}

__device__ __forceinline__ void split_f32(float x, __nv_bfloat16& hi, __nv_bfloat16& lo)
{
    hi = __float2bfloat16(x);
    lo = __float2bfloat16(x - __bfloat162float(hi));
}

// ---------------------------------------------------------------------------
// prep_x: split X [NROW,DIN] fp32 -> hi/lo bf16 (once)
// ---------------------------------------------------------------------------
__global__ __launch_bounds__(256) void prep_x(const float* __restrict__ X)
{
    int id = blockIdx.x * 256 + threadIdx.x;      // one float4 per thread
    float4 v = *(const float4*)&X[(size_t)id * 4];
    __nv_bfloat16 h0, h1, h2, h3, l0, l1, l2, l3;
    split_f32(v.x, h0, l0); split_f32(v.y, h1, l1);
    split_f32(v.z, h2, l2); split_f32(v.w, h3, l3);
    *(uint2*)&g_XHi[(size_t)id * 4] = make_uint2(pack_bf2(h0,h1), pack_bf2(h2,h3));
    *(uint2*)&g_XLo[(size_t)id * 4] = make_uint2(pack_bf2(l0,l1), pack_bf2(l2,l3));
}

// ---------------------------------------------------------------------------
// prep_w: W[h][d][e] -> W2[which][d][h*64+e], split hi/lo. Wq scaled by 0.125
// (folds the attention 1/sqrt(64) into the Q projection; exact, power of 2).
// ---------------------------------------------------------------------------
__global__ __launch_bounds__(256) void prep_w(
    const float* __restrict__ Wq,
    const float* __restrict__ Wk,
    const float* __restrict__ Wv)
{
    const int which = blockIdx.y;
    const float* W = (which == 0) ? Wq : ((which == 1) ? Wk : Wv);
    const float sc = (which == 0) ? 0.125f : 1.0f;

    int id = blockIdx.x * 256 + threadIdx.x;      // one 4-elem group
    int n4 = id & 255;                            // n = n4*4
    int d  = id >> 8;                             // 0..1023
    int h  = n4 >> 4;                             // n/64
    int e  = (n4 & 15) * 4;                       // n%64

    float4 v = *(const float4*)&W[((size_t)h * DIN_ + d) * E_ + e];
    v.x *= sc; v.y *= sc; v.z *= sc; v.w *= sc;
    __nv_bfloat16 h0, h1, h2, h3, l0, l1, l2, l3;
    split_f32(v.x, h0, l0); split_f32(v.y, h1, l1);
    split_f32(v.z, h2, l2); split_f32(v.w, h3, l3);
    size_t dst = (size_t)which * DIN_ * NOUT + (size_t)d * NOUT + n4 * 4;
    *(uint2*)&g_WHi[dst] = make_uint2(pack_bf2(h0,h1), pack_bf2(h2,h3));
    *(uint2*)&g_WLo[dst] = make_uint2(pack_bf2(l0,l1), pack_bf2(l2,l3));
}

// ---------------------------------------------------------------------------
// proj: [NROW,DIN] x [DIN,NOUT] -> pre-split Q/K/V, bf16 x3 split MMA.
// Block tile 128x128, K-tile 32. 256 threads = 8 warps (4 M x 2 N).
// Warp tile 32(M) x 64(N) = 2 m16 x 8 n8.
// ---------------------------------------------------------------------------
#define PA_STR 40    // A smem row elems (32+8) -> 80B, ldsm conflict-free
#define PB_STR 136   // B smem row elems (128+8) -> 272B, conflict-free

__global__ __launch_bounds__(256) void proj_mma_kernel()
{
    __shared__ __nv_bfloat16 AHi[128 * PA_STR], ALo[128 * PA_STR];
    __shared__ __nv_bfloat16 BHi[32 * PB_STR],  BLo[32 * PB_STR];

    const int tid  = threadIdx.x;
    const int wid  = tid >> 5;
    const int lane = tid & 31;
    const int wm = wid >> 1;       // 0..3
    const int wn = wid & 1;        // 0..1

    const int which = blockIdx.z;
    const int m0 = blockIdx.x * 128;
    const int n0 = blockIdx.y * 128;

    const __nv_bfloat16* Whi = g_WHi + (size_t)which * DIN_ * NOUT;
    const __nv_bfloat16* Wlo = g_WLo + (size_t)which * DIN_ * NOUT;
    __nv_bfloat16* OHi = (which == 0) ? g_QHi : ((which == 1) ? g_KHi : g_VHi);
    __nv_bfloat16* OLo = (which == 0) ? g_QLo : ((which == 1) ? g_KLo : g_VLo);

    float c[2][8][4];
    #pragma unroll
    for (int mi = 0; mi < 2; mi++)
        #pragma unroll
        for (int ni = 0; ni < 8; ni++)
            #pragma unroll
            for (int r = 0; r < 4; r++) c[mi][ni][r] = 0.f;

    const int lrow  = lane & 15;
    const int lcol8 = (lane >> 4) * 8;

    const uint32_t ahiB = (uint32_t)__cvta_generic_to_shared(AHi);
    const uint32_t aloB = (uint32_t)__cvta_generic_to_shared(ALo);
    const uint32_t bhiB = (uint32_t)__cvta_generic_to_shared(BHi);
    const uint32_t bloB = (uint32_t)__cvta_generic_to_shared(BLo);

    uint32_t offA[2];
    #pragma unroll
    for (int mi = 0; mi < 2; mi++)
        offA[mi] = (uint32_t)(((wm * 32 + mi * 16 + lrow) * PA_STR + lcol8) * 2);
    uint32_t offB[4];
    #pragma unroll
    for (int nt = 0; nt < 4; nt++)
        offB[nt] = (uint32_t)((lrow * PB_STR + wn * 64 + nt * 16 + lcol8) * 2);

    for (int k0 = 0; k0 < DIN_; k0 += 32) {
        // A tile: 128x32 bf16 hi+lo, 2 uint4 per thread per buffer
        #pragma unroll
        for (int j = 0; j < 2; j++) {
            int id  = tid + 256 * j;        // 0..511
            int row = id >> 2;              // 0..127
            int seg = (id & 3) * 8;         // 0,8,16,24
            size_t src = (size_t)(m0 + row) * DIN_ + k0 + seg;
            *(uint4*)&AHi[row * PA_STR + seg] = *(const uint4*)&g_XHi[src];
            *(uint4*)&ALo[row * PA_STR + seg] = *(const uint4*)&g_XLo[src];
        }
        // B tile: 32x128 bf16 hi+lo
        #pragma unroll
        for (int j = 0; j < 2; j++) {
            int id  = tid + 256 * j;        // 0..511
            int row = id >> 4;              // 0..31
            int seg = (id & 15) * 8;        // 0..120
            size_t src = (size_t)(k0 + row) * NOUT + n0 + seg;
            *(uint4*)&BHi[row * PB_STR + seg] = *(const uint4*)&Whi[src];
            *(uint4*)&BLo[row * PB_STR + seg] = *(const uint4*)&Wlo[src];
        }
        __syncthreads();

        #pragma unroll
        for (int ks = 0; ks < 2; ks++) {
            const uint32_t aKoff = (uint32_t)(ks * 16 * 2);
            const uint32_t bKoff = (uint32_t)(ks * 16 * PB_STR * 2);

            uint32_t ah[2][4], al[2][4];
            #pragma unroll
            for (int mi = 0; mi < 2; mi++) {
                ldsm_x4(ah[mi][0], ah[mi][1], ah[mi][2], ah[mi][3], ahiB + offA[mi] + aKoff);
                ldsm_x4(al[mi][0], al[mi][1], al[mi][2], al[mi][3], aloB + offA[mi] + aKoff);
            }
            #pragma unroll
            for (int nt = 0; nt < 4; nt++) {
                uint32_t h0, h1, h2, h3, l0, l1, l2, l3;
                ldsm_x4_t(h0, h1, h2, h3, bhiB + offB[nt] + bKoff);
                ldsm_x4_t(l0, l1, l2, l3, bloB + offB[nt] + bKoff);
                #pragma unroll
                for (int mi = 0; mi < 2; mi++) {
                    mma_bf16_16816(c[mi][2*nt],   ah[mi], h0, h1);
                    mma_bf16_16816(c[mi][2*nt],   ah[mi], l0, l1);
                    mma_bf16_16816(c[mi][2*nt],   al[mi], h0, h1);
                    mma_bf16_16816(c[mi][2*nt+1], ah[mi], h2, h3);
                    mma_bf16_16816(c[mi][2*nt+1], ah[mi], l2, l3);
                    mma_bf16_16816(c[mi][2*nt+1], al[mi], h2, h3);
                }
            }
        }
        __syncthreads();
    }

    // epilogue: split accumulators, store hi/lo bf16
    const int crow = lane >> 2;
    const int ccol = (lane & 3) * 2;
    #pragma unroll
    for (int mi = 0; mi < 2; mi++) {
        #pragma unroll
        for (int ni = 0; ni < 8; ni++) {
            int row = m0 + wm * 32 + mi * 16 + crow;
            int col = n0 + wn * 64 + ni * 8 + ccol;
            __nv_bfloat16 h0, h1, l0, l1;
            split_f32(c[mi][ni][0], h0, l0);
            split_f32(c[mi][ni][1], h1, l1);
            *(uint32_t*)&OHi[(size_t)row * NOUT + col] = pack_bf2(h0, h1);
            *(uint32_t*)&OLo[(size_t)row * NOUT + col] = pack_bf2(l0, l1);
            split_f32(c[mi][ni][2], h0, l0);
            split_f32(c[mi][ni][3], h1, l1);
            *(uint32_t*)&OHi[(size_t)(row + 8) * NOUT + col] = pack_bf2(h0, h1);
            *(uint32_t*)&OLo[(size_t)(row + 8) * NOUT + col] = pack_bf2(l0, l1);
        }
    }
}

// ---------------------------------------------------------------------------
// attn: causal flash attention, bf16 x3 split MMA, pre-split Q/K/V inputs.
// Block = (64 q rows, h, b); 128 threads = 4 warps; warp w owns rows w*16..+15.
// ---------------------------------------------------------------------------
#define A_STR 72    // 144B rows, ldsm conflict-free

__global__ __launch_bounds__(128) void attn_mma_kernel(float* __restrict__ out)
{
    __shared__ __nv_bfloat16 QHi[64 * A_STR], QLo[64 * A_STR];
    __shared__ __nv_bfloat16 KHi[32 * A_STR], KLo[32 * A_STR];
    __shared__ __nv_bfloat16 VHi[32 * A_STR], VLo[32 * A_STR];

    const int tid  = threadIdx.x;
    const int lane = tid & 31;
    const int wid  = tid >> 5;          // 0..3
    const int qt = blockIdx.x;          // 0..31
    const int h  = blockIdx.y;
    const int b  = blockIdx.z;
    const size_t rbase = (size_t)b * S_;        // global row base
    const int    cbase = h * E_;                // global col base
    const int qbase = qt * 64;

    // stage Q (already scaled via Wq): pure copies
    #pragma unroll
    for (int t = 0; t < 4; t++) {
        int id  = tid + 128 * t;        // 0..511
        int row = id >> 3;              // 0..63
        int seg = (id & 7) * 8;         // 0..56
        size_t src = (rbase + qbase + row) * NOUT + cbase + seg;
        *(uint4*)&QHi[row * A_STR + seg] = *(const uint4*)&g_QHi[src];
        *(uint4*)&QLo[row * A_STR + seg] = *(const uint4*)&g_QLo[src];
    }
    __syncthreads();

    const uint32_t qhiB = (uint32_t)__cvta_generic_to_shared(QHi);
    const uint32_t qloB = (uint32_t)__cvta_generic_to_shared(QLo);
    const uint32_t khiB = (uint32_t)__cvta_generic_to_shared(KHi);
    const uint32_t kloB = (uint32_t)__cvta_generic_to_shared(KLo);
    const uint32_t vhiB = (uint32_t)__cvta_generic_to_shared(VHi);
    const uint32_t vloB = (uint32_t)__cvta_generic_to_shared(VLo);

    const int lrow  = lane & 15;
    const int lcol8 = (lane >> 4) * 8;

    // Q fragments: A layout, 4 k16 steps over E=64, held for whole kernel
    uint32_t qh[4][4], ql[4][4];
    #pragma unroll
    for (int ks = 0; ks < 4; ks++) {
        uint32_t off = (uint32_t)(((wid * 16 + lrow) * A_STR + ks * 16 + lcol8) * 2);
        ldsm_x4(qh[ks][0], qh[ks][1], qh[ks][2], qh[ks][3], qhiB + off);
        ldsm_x4(ql[ks][0], ql[ks][1], ql[ks][2], ql[ks][3], qloB + off);
    }

    float o[8][4];
    #pragma unroll
    for (int nt = 0; nt < 8; nt++)
        #pragma unroll
        for (int r = 0; r < 4; r++) o[nt][r] = 0.f;
    float mr0 = -1e30f, mr1 = -1e30f, lr0 = 0.f, lr1 = 0.f;

    // K non-trans B-frag address pieces: rows = keys, cols = e
    const int knrow = (lane & 7) + ((lane >> 4) & 1) * 8;
    const int kksel = ((lane >> 3) & 1) * 8;

    const int nkt = 2 * qt + 2;
    for (int kt = 0; kt < nkt; kt++) {
        const int kbase = kt * 32;
        __syncthreads();   // prior-iter smem reads done before overwrite

        // K/V tiles 32x64: pure copies (pre-split)
        #pragma unroll
        for (int t = 0; t < 2; t++) {
            int id  = tid + 128 * t;    // 0..255
            int row = id >> 3;          // 0..31
            int seg = (id & 7) * 8;
            size_t src = (rbase + kbase + row) * NOUT + cbase + seg;
            *(uint4*)&KHi[row * A_STR + seg] = *(const uint4*)&g_KHi[src];
            *(uint4*)&KLo[row * A_STR + seg] = *(const uint4*)&g_KLo[src];
            *(uint4*)&VHi[row * A_STR + seg] = *(const uint4*)&g_VHi[src];
            *(uint4*)&VLo[row * A_STR + seg] = *(const uint4*)&g_VLo[src];
        }
        __syncthreads();

        // warp skips tiles entirely above its causal diagonal
        if (kbase > qbase + wid * 16 + 15) continue;

        // ---- S = Q @ K^T (4 n8-tiles over 32 keys) ----
        float s[4][4];
        #pragma unroll
        for (int nt = 0; nt < 4; nt++)
            #pragma unroll
            for (int r = 0; r < 4; r++) s[nt][r] = 0.f;

        #pragma unroll
        for (int ks = 0; ks < 4; ks++) {
            uint32_t kbh[4][2], kbl[4][2];
            #pragma unroll
            for (int np = 0; np < 2; np++) {
                uint32_t off = (uint32_t)(((np * 16 + knrow) * A_STR + ks * 16 + kksel) * 2);
                uint32_t r0, r1, r2, r3;
                ldsm_x4(r0, r1, r2, r3, khiB + off);
                kbh[2*np][0] = r0; kbh[2*np][1] = r1; kbh[2*np+1][0] = r2; kbh[2*np+1][1] = r3;
                ldsm_x4(r0, r1, r2, r3, kloB + off);
                kbl[2*np][0] = r0; kbl[2*np][1] = r1; kbl[2*np+1][0] = r2; kbl[2*np+1][1] = r3;
            }
            #pragma unroll
            for (int nt = 0; nt < 4; nt++) {
                mma_bf16_16816(s[nt], qh[ks], kbh[nt][0], kbh[nt][1]);
                mma_bf16_16816(s[nt], qh[ks], kbl[nt][0], kbl[nt][1]);
                mma_bf16_16816(s[nt], ql[ks], kbh[nt][0], kbh[nt][1]);
            }
        }

        // ---- causal mask ----
        if (kbase + 31 > qbase + wid * 16) {
            int row0 = qbase + wid * 16 + (lane >> 2);
            #pragma unroll
            for (int nt = 0; nt < 4; nt++) {
                int colb = kbase + nt * 8 + (lane & 3) * 2;
                if (colb     > row0)     s[nt][0] = -1e30f;
                if (colb + 1 > row0)     s[nt][1] = -1e30f;
                if (colb     > row0 + 8) s[nt][2] = -1e30f;
                if (colb + 1 > row0 + 8) s[nt][3] = -1e30f;
            }
        }

        // ---- online softmax ----
        float mx0 = fmaxf(fmaxf(s[0][0], s[0][1]), fmaxf(s[1][0], s[1][1]));
        mx0 = fmaxf(mx0, fmaxf(fmaxf(s[2][0], s[2][1]), fmaxf(s[3][0], s[3][1])));
        float mx1 = fmaxf(fmaxf(s[0][2], s[0][3]), fmaxf(s[1][2], s[1][3]));
        mx1 = fmaxf(mx1, fmaxf(fmaxf(s[2][2], s[2][3]), fmaxf(s[3][2], s[3][3])));
        mx0 = fmaxf(mx0, __shfl_xor_sync(0xffffffffu, mx0, 1));
        mx0 = fmaxf(mx0, __shfl_xor_sync(0xffffffffu, mx0, 2));
        mx1 = fmaxf(mx1, __shfl_xor_sync(0xffffffffu, mx1, 1));
        mx1 = fmaxf(mx1, __shfl_xor_sync(0xffffffffu, mx1, 2));

        float mn0 = fmaxf(mr0, mx0), mn1 = fmaxf(mr1, mx1);
        float a0 = __expf(mr0 - mn0), a1 = __expf(mr1 - mn1);

        float p[4][4];
        float rs0 = 0.f, rs1 = 0.f;
        #pragma unroll
        for (int nt = 0; nt < 4; nt++) {
            p[nt][0] = __expf(s[nt][0] - mn0);
            p[nt][1] = __expf(s[nt][1] - mn0);
            p[nt][2] = __expf(s[nt][2] - mn1);
            p[nt][3] = __expf(s[nt][3] - mn1);
            rs0 += p[nt][0] + p[nt][1];
            rs1 += p[nt][2] + p[nt][3];
        }
        rs0 += __shfl_xor_sync(0xffffffffu, rs0, 1);
        rs0 += __shfl_xor_sync(0xffffffffu, rs0, 2);
        rs1 += __shfl_xor_sync(0xffffffffu, rs1, 1);
        rs1 += __shfl_xor_sync(0xffffffffu, rs1, 2);
        lr0 = lr0 * a0 + rs0;  lr1 = lr1 * a1 + rs1;
        mr0 = mn0;             mr1 = mn1;

        #pragma unroll
        for (int nt = 0; nt < 8; nt++) {
            o[nt][0] *= a0; o[nt][1] *= a0;
            o[nt][2] *= a1; o[nt][3] *= a1;
        }

        // ---- pack P as split A-fragments (2 k16 steps over 32 keys) ----
        uint32_t ph[2][4], pl[2][4];
        #pragma unroll
        for (int ksp = 0; ksp < 2; ksp++) {
            #pragma unroll
            for (int half = 0; half < 2; half++) {
                int nt = 2 * ksp + half;
                __nv_bfloat16 h0, h1, h2, h3, l0, l1, l2, l3;
                split_f32(p[nt][0], h0, l0); split_f32(p[nt][1], h1, l1);
                split_f32(p[nt][2], h2, l2); split_f32(p[nt][3], h3, l3);
                ph[ksp][2*half]     = pack_bf2(h0, h1);
                ph[ksp][2*half + 1] = pack_bf2(h2, h3);
                pl[ksp][2*half]     = pack_bf2(l0, l1);
                pl[ksp][2*half + 1] = pack_bf2(l2, l3);
            }
        }

        // ---- O += P @ V (8 n8-tiles over E=64) ----
        #pragma unroll
        for (int ksp = 0; ksp < 2; ksp++) {
            #pragma unroll
            for (int ep = 0; ep < 4; ep++) {
                uint32_t off = (uint32_t)(((ksp * 16 + lrow) * A_STR + ep * 16 + lcol8) * 2);
                uint32_t vh0, vh1, vh2, vh3, vl0, vl1, vl2, vl3;
                ldsm_x4_t(vh0, vh1, vh2, vh3, vhiB + off);
                ldsm_x4_t(vl0, vl1, vl2, vl3, vloB + off);
                mma_bf16_16816(o[2*ep],   ph[ksp], vh0, vh1);
                mma_bf16_16816(o[2*ep],   ph[ksp], vl0, vl1);
                mma_bf16_16816(o[2*ep],   pl[ksp], vh0, vh1);
                mma_bf16_16816(o[2*ep+1], ph[ksp], vh2, vh3);
                mma_bf16_16816(o[2*ep+1], ph[ksp], vl2, vl3);
                mma_bf16_16816(o[2*ep+1], pl[ksp], vh2, vh3);
            }
        }
    }

    // ---- epilogue ----
    float inv0 = 1.f / lr0, inv1 = 1.f / lr1;
    int row0 = qbase + wid * 16 + (lane >> 2);
    int colb = (lane & 3) * 2;
    #pragma unroll
    for (int nt = 0; nt < 8; nt++) {
        int col = cbase + nt * 8 + colb;
        *(float2*)&out[(rbase + row0) * (size_t)NOUT + col] =
            make_float2(o[nt][0] * inv0, o[nt][1] * inv0);
        *(float2*)&out[(rbase + row0 + 8) * (size_t)NOUT + col] =
            make_float2(o[nt][2] * inv1, o[nt][3] * inv1);
    }
}

extern "C" void kernel_launch(void* const* d_in, const int* in_sizes, int n_in,
                              void* d_out, int out_size)
{
    const float* x  = (const float*)d_in[0];
    const float* wq = (const float*)d_in[1];
    const float* wk = (const float*)d_in[2];
    const float* wv = (const float*)d_in[3];
    float* out = (float*)d_out;

    prep_x<<<NROW * DIN_ / 1024, 256>>>(x);
    prep_w<<<dim3(DIN_ * NOUT / 1024, 3), 256>>>(wq, wk, wv);

    dim3 gp(NROW / 128, NOUT / 128, 3);
    proj_mma_kernel<<<gp, 256>>>();

    dim3 ga(S_ / 64, H_, B_);
    attn_mma_kernel<<<ga, 128>>>(out);
}

// round 16
// speedup vs baseline: 1.0693x; 1.0133x over previous
#include <cuda_runtime.h>
#include <cuda_bf16.h>
#include <cstdint>

#define B_ 4
#define S_ 2048
#define DIN_ 1024
#define H_ 16
#define E_ 64
#define NROW (B_*S_)     // 8192 rows (b,s)
#define NOUT (H_*E_)     // 1024 cols (h,e)

// Pre-split operands (bf16 hi/lo), produced once per launch
__device__ __nv_bfloat16 g_XHi[NROW*DIN_], g_XLo[NROW*DIN_];
__device__ __nv_bfloat16 g_WHi[3*DIN_*NOUT], g_WLo[3*DIN_*NOUT];
// Q/K/V stored pre-split as [NROW][NOUT] (row = b*S+s, col = h*64+e)
__device__ __nv_bfloat16 g_QHi[NROW*NOUT], g_QLo[NROW*NOUT];
__device__ __nv_bfloat16 g_KHi[NROW*NOUT], g_KLo[NROW*NOUT];
__device__ __nv_bfloat16 g_VHi[NROW*NOUT], g_VLo[NROW*NOUT];

// ---------------------------------------------------------------------------
// helpers
// ---------------------------------------------------------------------------
__device__ __forceinline__ void mma_bf16_16816(float c[4],
    const uint32_t a[4], uint32_t b0, uint32_t b1)
{
    asm volatile(
        "mma.sync.aligned.m16n8k16.row.col.f32.bf16.bf16.f32 "
        "{%0,%1,%2,%3}, {%4,%5,%6,%7}, {%8,%9}, {%0,%1,%2,%3};"
        : "+f"(c[0]), "+f"(c[1]), "+f"(c[2]), "+f"(c[3])
        : "r"(a[0]), "r"(a[1]), "r"(a[2]), "r"(a[3]), "r"(b0), "r"(b1));
}

__device__ __forceinline__ void ldsm_x4(uint32_t& r0, uint32_t& r1,
                                        uint32_t& r2, uint32_t& r3, uint32_t addr)
{
    asm volatile("ldmatrix.sync.aligned.m8n8.x4.shared.b16 {%0,%1,%2,%3}, [%4];"
                 : "=r"(r0), "=r"(r1), "=r"(r2), "=r"(r3) : "r"(addr));
}

__device__ __forceinline__ void ldsm_x4_t(uint32_t& r0, uint32_t& r1,
                                          uint32_t& r2, uint32_t& r3, uint32_t addr)
{
    asm volatile("ldmatrix.sync.aligned.m8n8.x4.trans.shared.b16 {%0,%1,%2,%3}, [%4];"
                 : "=r"(r0), "=r"(r1), "=r"(r2), "=r"(r3) : "r"(addr));
}

__device__ __forceinline__ uint32_t pack_bf2(__nv_bfloat16 a, __nv_bfloat16 b)
{
    __nv_bfloat162 t = __halves2bfloat162(a, b);   // a = low half, b = high half
    return *reinterpret_cast<uint32_t*>(&t);
}

__device__ __forceinline__ void split_f32(float x, __nv_bfloat16& hi, __nv_bfloat16& lo)
{
    hi = __float2bfloat16(x);
    lo = __float2bfloat16(x - __bfloat162float(hi));
}

// ---------------------------------------------------------------------------
// prep_x: split X [NROW,DIN] fp32 -> hi/lo bf16 (once)
// ---------------------------------------------------------------------------
__global__ __launch_bounds__(256) void prep_x(const float* __restrict__ X)
{
    int id = blockIdx.x * 256 + threadIdx.x;      // one float4 per thread
    float4 v = *(const float4*)&X[(size_t)id * 4];
    __nv_bfloat16 h0, h1, h2, h3, l0, l1, l2, l3;
    split_f32(v.x, h0, l0); split_f32(v.y, h1, l1);
    split_f32(v.z, h2, l2); split_f32(v.w, h3, l3);
    *(uint2*)&g_XHi[(size_t)id * 4] = make_uint2(pack_bf2(h0,h1), pack_bf2(h2,h3));
    *(uint2*)&g_XLo[(size_t)id * 4] = make_uint2(pack_bf2(l0,l1), pack_bf2(l2,l3));
}

// ---------------------------------------------------------------------------
// prep_w: W[h][d][e] -> W2[which][d][h*64+e], split hi/lo. Wq scaled by 0.125
// (folds the attention 1/sqrt(64) into the Q projection; exact, power of 2).
// ---------------------------------------------------------------------------
__global__ __launch_bounds__(256) void prep_w(
    const float* __restrict__ Wq,
    const float* __restrict__ Wk,
    const float* __restrict__ Wv)
{
    const int which = blockIdx.y;
    const float* W = (which == 0) ? Wq : ((which == 1) ? Wk : Wv);
    const float sc = (which == 0) ? 0.125f : 1.0f;

    int id = blockIdx.x * 256 + threadIdx.x;      // one 4-elem group
    int n4 = id & 255;                            // n = n4*4
    int d  = id >> 8;                             // 0..1023
    int h  = n4 >> 4;                             // n/64
    int e  = (n4 & 15) * 4;                       // n%64

    float4 v = *(const float4*)&W[((size_t)h * DIN_ + d) * E_ + e];
    v.x *= sc; v.y *= sc; v.z *= sc; v.w *= sc;
    __nv_bfloat16 h0, h1, h2, h3, l0, l1, l2, l3;
    split_f32(v.x, h0, l0); split_f32(v.y, h1, l1);
    split_f32(v.z, h2, l2); split_f32(v.w, h3, l3);
    size_t dst = (size_t)which * DIN_ * NOUT + (size_t)d * NOUT + n4 * 4;
    *(uint2*)&g_WHi[dst] = make_uint2(pack_bf2(h0,h1), pack_bf2(h2,h3));
    *(uint2*)&g_WLo[dst] = make_uint2(pack_bf2(l0,l1), pack_bf2(l2,l3));
}

// ---------------------------------------------------------------------------
// proj: [NROW,DIN] x [DIN,NOUT] -> pre-split Q/K/V, bf16 x3 split MMA.
// Block tile 128x128, K-tile 32. 256 threads = 8 warps (4 M x 2 N).
// Warp tile 32(M) x 64(N) = 2 m16 x 8 n8.
// __launch_bounds__(256, 2): cap at 128 regs so 2 CTAs/SM co-reside
// (2 x 256 x 128 = 65536 = full RF), doubling warps to cover sync/load gaps.
// ---------------------------------------------------------------------------
#define PA_STR 40    // A smem row elems (32+8) -> 80B, ldsm conflict-free
#define PB_STR 136   // B smem row elems (128+8) -> 272B, conflict-free

__global__ __launch_bounds__(256, 2) void proj_mma_kernel()
{
    __shared__ __nv_bfloat16 AHi[128 * PA_STR], ALo[128 * PA_STR];
    __shared__ __nv_bfloat16 BHi[32 * PB_STR],  BLo[32 * PB_STR];

    const int tid  = threadIdx.x;
    const int wid  = tid >> 5;
    const int lane = tid & 31;
    const int wm = wid >> 1;       // 0..3
    const int wn = wid & 1;        // 0..1

    const int which = blockIdx.z;
    const int m0 = blockIdx.x * 128;
    const int n0 = blockIdx.y * 128;

    const __nv_bfloat16* Whi = g_WHi + (size_t)which * DIN_ * NOUT;
    const __nv_bfloat16* Wlo = g_WLo + (size_t)which * DIN_ * NOUT;
    __nv_bfloat16* OHi = (which == 0) ? g_QHi : ((which == 1) ? g_KHi : g_VHi);
    __nv_bfloat16* OLo = (which == 0) ? g_QLo : ((which == 1) ? g_KLo : g_VLo);

    float c[2][8][4];
    #pragma unroll
    for (int mi = 0; mi < 2; mi++)
        #pragma unroll
        for (int ni = 0; ni < 8; ni++)
            #pragma unroll
            for (int r = 0; r < 4; r++) c[mi][ni][r] = 0.f;

    const int lrow  = lane & 15;
    const int lcol8 = (lane >> 4) * 8;

    const uint32_t ahiB = (uint32_t)__cvta_generic_to_shared(AHi);
    const uint32_t aloB = (uint32_t)__cvta_generic_to_shared(ALo);
    const uint32_t bhiB = (uint32_t)__cvta_generic_to_shared(BHi);
    const uint32_t bloB = (uint32_t)__cvta_generic_to_shared(BLo);

    uint32_t offA[2];
    #pragma unroll
    for (int mi = 0; mi < 2; mi++)
        offA[mi] = (uint32_t)(((wm * 32 + mi * 16 + lrow) * PA_STR + lcol8) * 2);
    uint32_t offB[4];
    #pragma unroll
    for (int nt = 0; nt < 4; nt++)
        offB[nt] = (uint32_t)((lrow * PB_STR + wn * 64 + nt * 16 + lcol8) * 2);

    for (int k0 = 0; k0 < DIN_; k0 += 32) {
        // A tile: 128x32 bf16 hi+lo, 2 uint4 per thread per buffer
        #pragma unroll
        for (int j = 0; j < 2; j++) {
            int id  = tid + 256 * j;        // 0..511
            int row = id >> 2;              // 0..127
            int seg = (id & 3) * 8;         // 0,8,16,24
            size_t src = (size_t)(m0 + row) * DIN_ + k0 + seg;
            *(uint4*)&AHi[row * PA_STR + seg] = *(const uint4*)&g_XHi[src];
            *(uint4*)&ALo[row * PA_STR + seg] = *(const uint4*)&g_XLo[src];
        }
        // B tile: 32x128 bf16 hi+lo
        #pragma unroll
        for (int j = 0; j < 2; j++) {
            int id  = tid + 256 * j;        // 0..511
            int row = id >> 4;              // 0..31
            int seg = (id & 15) * 8;        // 0..120
            size_t src = (size_t)(k0 + row) * NOUT + n0 + seg;
            *(uint4*)&BHi[row * PB_STR + seg] = *(const uint4*)&Whi[src];
            *(uint4*)&BLo[row * PB_STR + seg] = *(const uint4*)&Wlo[src];
        }
        __syncthreads();

        #pragma unroll
        for (int ks = 0; ks < 2; ks++) {
            const uint32_t aKoff = (uint32_t)(ks * 16 * 2);
            const uint32_t bKoff = (uint32_t)(ks * 16 * PB_STR * 2);

            uint32_t ah[2][4], al[2][4];
            #pragma unroll
            for (int mi = 0; mi < 2; mi++) {
                ldsm_x4(ah[mi][0], ah[mi][1], ah[mi][2], ah[mi][3], ahiB + offA[mi] + aKoff);
                ldsm_x4(al[mi][0], al[mi][1], al[mi][2], al[mi][3], aloB + offA[mi] + aKoff);
            }
            #pragma unroll
            for (int nt = 0; nt < 4; nt++) {
                uint32_t h0, h1, h2, h3, l0, l1, l2, l3;
                ldsm_x4_t(h0, h1, h2, h3, bhiB + offB[nt] + bKoff);
                ldsm_x4_t(l0, l1, l2, l3, bloB + offB[nt] + bKoff);
                #pragma unroll
                for (int mi = 0; mi < 2; mi++) {
                    mma_bf16_16816(c[mi][2*nt],   ah[mi], h0, h1);
                    mma_bf16_16816(c[mi][2*nt],   ah[mi], l0, l1);
                    mma_bf16_16816(c[mi][2*nt],   al[mi], h0, h1);
                    mma_bf16_16816(c[mi][2*nt+1], ah[mi], h2, h3);
                    mma_bf16_16816(c[mi][2*nt+1], ah[mi], l2, l3);
                    mma_bf16_16816(c[mi][2*nt+1], al[mi], h2, h3);
                }
            }
        }
        __syncthreads();
    }

    // epilogue: split accumulators, store hi/lo bf16
    const int crow = lane >> 2;
    const int ccol = (lane & 3) * 2;
    #pragma unroll
    for (int mi = 0; mi < 2; mi++) {
        #pragma unroll
        for (int ni = 0; ni < 8; ni++) {
            int row = m0 + wm * 32 + mi * 16 + crow;
            int col = n0 + wn * 64 + ni * 8 + ccol;
            __nv_bfloat16 h0, h1, l0, l1;
            split_f32(c[mi][ni][0], h0, l0);
            split_f32(c[mi][ni][1], h1, l1);
            *(uint32_t*)&OHi[(size_t)row * NOUT + col] = pack_bf2(h0, h1);
            *(uint32_t*)&OLo[(size_t)row * NOUT + col] = pack_bf2(l0, l1);
            split_f32(c[mi][ni][2], h0, l0);
            split_f32(c[mi][ni][3], h1, l1);
            *(uint32_t*)&OHi[(size_t)(row + 8) * NOUT + col] = pack_bf2(h0, h1);
            *(uint32_t*)&OLo[(size_t)(row + 8) * NOUT + col] = pack_bf2(l0, l1);
        }
    }
}

// ---------------------------------------------------------------------------
// attn: causal flash attention, bf16 x3 split MMA, pre-split Q/K/V inputs.
// Block = (64 q rows, h, b); 128 threads = 4 warps; warp w owns rows w*16..+15.
// __launch_bounds__(128, 4): measured 130 regs / 3 CTAs / occ 17.4%; cap to
// 128 regs so 4 CTAs co-reside (4 x 128 x 128 = 65536 = full RF) -> 16 warps.
// ---------------------------------------------------------------------------
#define A_STR 72    // 144B rows, ldsm conflict-free

__global__ __launch_bounds__(128, 4) void attn_mma_kernel(float* __restrict__ out)
{
    __shared__ __nv_bfloat16 QHi[64 * A_STR], QLo[64 * A_STR];
    __shared__ __nv_bfloat16 KHi[32 * A_STR], KLo[32 * A_STR];
    __shared__ __nv_bfloat16 VHi[32 * A_STR], VLo[32 * A_STR];

    const int tid  = threadIdx.x;
    const int lane = tid & 31;
    const int wid  = tid >> 5;          // 0..3
    const int qt = blockIdx.x;          // 0..31
    const int h  = blockIdx.y;
    const int b  = blockIdx.z;
    const size_t rbase = (size_t)b * S_;        // global row base
    const int    cbase = h * E_;                // global col base
    const int qbase = qt * 64;

    // stage Q (already scaled via Wq): pure copies
    #pragma unroll
    for (int t = 0; t < 4; t++) {
        int id  = tid + 128 * t;        // 0..511
        int row = id >> 3;              // 0..63
        int seg = (id & 7) * 8;         // 0..56
        size_t src = (rbase + qbase + row) * NOUT + cbase + seg;
        *(uint4*)&QHi[row * A_STR + seg] = *(const uint4*)&g_QHi[src];
        *(uint4*)&QLo[row * A_STR + seg] = *(const uint4*)&g_QLo[src];
    }
    __syncthreads();

    const uint32_t qhiB = (uint32_t)__cvta_generic_to_shared(QHi);
    const uint32_t qloB = (uint32_t)__cvta_generic_to_shared(QLo);
    const uint32_t khiB = (uint32_t)__cvta_generic_to_shared(KHi);
    const uint32_t kloB = (uint32_t)__cvta_generic_to_shared(KLo);
    const uint32_t vhiB = (uint32_t)__cvta_generic_to_shared(VHi);
    const uint32_t vloB = (uint32_t)__cvta_generic_to_shared(VLo);

    const int lrow  = lane & 15;
    const int lcol8 = (lane >> 4) * 8;

    // Q fragments: A layout, 4 k16 steps over E=64, held for whole kernel
    uint32_t qh[4][4], ql[4][4];
    #pragma unroll
    for (int ks = 0; ks < 4; ks++) {
        uint32_t off = (uint32_t)(((wid * 16 + lrow) * A_STR + ks * 16 + lcol8) * 2);
        ldsm_x4(qh[ks][0], qh[ks][1], qh[ks][2], qh[ks][3], qhiB + off);
        ldsm_x4(ql[ks][0], ql[ks][1], ql[ks][2], ql[ks][3], qloB + off);
    }

    float o[8][4];
    #pragma unroll
    for (int nt = 0; nt < 8; nt++)
        #pragma unroll
        for (int r = 0; r < 4; r++) o[nt][r] = 0.f;
    float mr0 = -1e30f, mr1 = -1e30f, lr0 = 0.f, lr1 = 0.f;

    // K non-trans B-frag address pieces: rows = keys, cols = e
    const int knrow = (lane & 7) + ((lane >> 4) & 1) * 8;
    const int kksel = ((lane >> 3) & 1) * 8;

    const int nkt = 2 * qt + 2;
    for (int kt = 0; kt < nkt; kt++) {
        const int kbase = kt * 32;
        __syncthreads();   // prior-iter smem reads done before overwrite

        // K/V tiles 32x64: pure copies (pre-split)
        #pragma unroll
        for (int t = 0; t < 2; t++) {
            int id  = tid + 128 * t;    // 0..255
            int row = id >> 3;          // 0..31
            int seg = (id & 7) * 8;
            size_t src = (rbase + kbase + row) * NOUT + cbase + seg;
            *(uint4*)&KHi[row * A_STR + seg] = *(const uint4*)&g_KHi[src];
            *(uint4*)&KLo[row * A_STR + seg] = *(const uint4*)&g_KLo[src];
            *(uint4*)&VHi[row * A_STR + seg] = *(const uint4*)&g_VHi[src];
            *(uint4*)&VLo[row * A_STR + seg] = *(const uint4*)&g_VLo[src];
        }
        __syncthreads();

        // warp skips tiles entirely above its causal diagonal
        if (kbase > qbase + wid * 16 + 15) continue;

        // ---- S = Q @ K^T (4 n8-tiles over 32 keys) ----
        float s[4][4];
        #pragma unroll
        for (int nt = 0; nt < 4; nt++)
            #pragma unroll
            for (int r = 0; r < 4; r++) s[nt][r] = 0.f;

        #pragma unroll
        for (int ks = 0; ks < 4; ks++) {
            uint32_t kbh[4][2], kbl[4][2];
            #pragma unroll
            for (int np = 0; np < 2; np++) {
                uint32_t off = (uint32_t)(((np * 16 + knrow) * A_STR + ks * 16 + kksel) * 2);
                uint32_t r0, r1, r2, r3;
                ldsm_x4(r0, r1, r2, r3, khiB + off);
                kbh[2*np][0] = r0; kbh[2*np][1] = r1; kbh[2*np+1][0] = r2; kbh[2*np+1][1] = r3;
                ldsm_x4(r0, r1, r2, r3, kloB + off);
                kbl[2*np][0] = r0; kbl[2*np][1] = r1; kbl[2*np+1][0] = r2; kbl[2*np+1][1] = r3;
            }
            #pragma unroll
            for (int nt = 0; nt < 4; nt++) {
                mma_bf16_16816(s[nt], qh[ks], kbh[nt][0], kbh[nt][1]);
                mma_bf16_16816(s[nt], qh[ks], kbl[nt][0], kbl[nt][1]);
                mma_bf16_16816(s[nt], ql[ks], kbh[nt][0], kbh[nt][1]);
            }
        }

        // ---- causal mask ----
        if (kbase + 31 > qbase + wid * 16) {
            int row0 = qbase + wid * 16 + (lane >> 2);
            #pragma unroll
            for (int nt = 0; nt < 4; nt++) {
                int colb = kbase + nt * 8 + (lane & 3) * 2;
                if (colb     > row0)     s[nt][0] = -1e30f;
                if (colb + 1 > row0)     s[nt][1] = -1e30f;
                if (colb     > row0 + 8) s[nt][2] = -1e30f;
                if (colb + 1 > row0 + 8) s[nt][3] = -1e30f;
            }
        }

        // ---- online softmax ----
        float mx0 = fmaxf(fmaxf(s[0][0], s[0][1]), fmaxf(s[1][0], s[1][1]));
        mx0 = fmaxf(mx0, fmaxf(fmaxf(s[2][0], s[2][1]), fmaxf(s[3][0], s[3][1])));
        float mx1 = fmaxf(fmaxf(s[0][2], s[0][3]), fmaxf(s[1][2], s[1][3]));
        mx1 = fmaxf(mx1, fmaxf(fmaxf(s[2][2], s[2][3]), fmaxf(s[3][2], s[3][3])));
        mx0 = fmaxf(mx0, __shfl_xor_sync(0xffffffffu, mx0, 1));
        mx0 = fmaxf(mx0, __shfl_xor_sync(0xffffffffu, mx0, 2));
        mx1 = fmaxf(mx1, __shfl_xor_sync(0xffffffffu, mx1, 1));
        mx1 = fmaxf(mx1, __shfl_xor_sync(0xffffffffu, mx1, 2));

        float mn0 = fmaxf(mr0, mx0), mn1 = fmaxf(mr1, mx1);
        float a0 = __expf(mr0 - mn0), a1 = __expf(mr1 - mn1);

        float p[4][4];
        float rs0 = 0.f, rs1 = 0.f;
        #pragma unroll
        for (int nt = 0; nt < 4; nt++) {
            p[nt][0] = __expf(s[nt][0] - mn0);
            p[nt][1] = __expf(s[nt][1] - mn0);
            p[nt][2] = __expf(s[nt][2] - mn1);
            p[nt][3] = __expf(s[nt][3] - mn1);
            rs0 += p[nt][0] + p[nt][1];
            rs1 += p[nt][2] + p[nt][3];
        }
        rs0 += __shfl_xor_sync(0xffffffffu, rs0, 1);
        rs0 += __shfl_xor_sync(0xffffffffu, rs0, 2);
        rs1 += __shfl_xor_sync(0xffffffffu, rs1, 1);
        rs1 += __shfl_xor_sync(0xffffffffu, rs1, 2);
        lr0 = lr0 * a0 + rs0;  lr1 = lr1 * a1 + rs1;
        mr0 = mn0;             mr1 = mn1;

        #pragma unroll
        for (int nt = 0; nt < 8; nt++) {
            o[nt][0] *= a0; o[nt][1] *= a0;
            o[nt][2] *= a1; o[nt][3] *= a1;
        }

        // ---- pack P as split A-fragments (2 k16 steps over 32 keys) ----
        uint32_t ph[2][4], pl[2][4];
        #pragma unroll
        for (int ksp = 0; ksp < 2; ksp++) {
            #pragma unroll
            for (int half = 0; half < 2; half++) {
                int nt = 2 * ksp + half;
                __nv_bfloat16 h0, h1, h2, h3, l0, l1, l2, l3;
                split_f32(p[nt][0], h0, l0); split_f32(p[nt][1], h1, l1);
                split_f32(p[nt][2], h2, l2); split_f32(p[nt][3], h3, l3);
                ph[ksp][2*half]     = pack_bf2(h0, h1);
                ph[ksp][2*half + 1] = pack_bf2(h2, h3);
                pl[ksp][2*half]     = pack_bf2(l0, l1);
                pl[ksp][2*half + 1] = pack_bf2(l2, l3);
            }
        }

        // ---- O += P @ V (8 n8-tiles over E=64) ----
        #pragma unroll
        for (int ksp = 0; ksp < 2; ksp++) {
            #pragma unroll
            for (int ep = 0; ep < 4; ep++) {
                uint32_t off = (uint32_t)(((ksp * 16 + lrow) * A_STR + ep * 16 + lcol8) * 2);
                uint32_t vh0, vh1, vh2, vh3, vl0, vl1, vl2, vl3;
                ldsm_x4_t(vh0, vh1, vh2, vh3, vhiB + off);
                ldsm_x4_t(vl0, vl1, vl2, vl3, vloB + off);
                mma_bf16_16816(o[2*ep],   ph[ksp], vh0, vh1);
                mma_bf16_16816(o[2*ep],   ph[ksp], vl0, vl1);
                mma_bf16_16816(o[2*ep],   pl[ksp], vh0, vh1);
                mma_bf16_16816(o[2*ep+1], ph[ksp], vh2, vh3);
                mma_bf16_16816(o[2*ep+1], ph[ksp], vl2, vl3);
                mma_bf16_16816(o[2*ep+1], pl[ksp], vh2, vh3);
            }
        }
    }

    // ---- epilogue ----
    float inv0 = 1.f / lr0, inv1 = 1.f / lr1;
    int row0 = qbase + wid * 16 + (lane >> 2);
    int colb = (lane & 3) * 2;
    #pragma unroll
    for (int nt = 0; nt < 8; nt++) {
        int col = cbase + nt * 8 + colb;
        *(float2*)&out[(rbase + row0) * (size_t)NOUT + col] =
            make_float2(o[nt][0] * inv0, o[nt][1] * inv0);
        *(float2*)&out[(rbase + row0 + 8) * (size_t)NOUT + col] =
            make_float2(o[nt][2] * inv1, o[nt][3] * inv1);
    }
}

extern "C" void kernel_launch(void* const* d_in, const int* in_sizes, int n_in,
                              void* d_out, int out_size)
{
    const float* x  = (const float*)d_in[0];
    const float* wq = (const float*)d_in[1];
    const float* wk = (const float*)d_in[2];
    const float* wv = (const float*)d_in[3];
    float* out = (float*)d_out;

    prep_x<<<NROW * DIN_ / 1024, 256>>>(x);
    prep_w<<<dim3(DIN_ * NOUT / 1024, 3), 256>>>(wq, wk, wv);

    dim3 gp(NROW / 128, NOUT / 128, 3);
    proj_mma_kernel<<<gp, 256>>>();

    dim3 ga(S_ / 64, H_, B_);
    attn_mma_kernel<<<ga, 128>>>(out);
}